// round 3
// baseline (speedup 1.0000x reference)
#include <cuda_runtime.h>
#include <math.h>

// Problem constants (fixed shapes)
#define NN    299593      // total nodes, complete 8-ary tree, 7 levels
#define HH    128         // D_ENC
#define EMBD  128         // D_EMB
#define NIOU  384         // 3*H
#define DDEC  256
#define NPAR  37449       // nodes at levels 0..5 (all parents) = off[6]

// Scratch (device globals: allocation-free per harness rules)
__device__ float g_h [(size_t)NN  * HH];
__device__ float g_c [(size_t)NN  * HH];
__device__ float g_xf[(size_t)NPAR * HH];
__device__ float g_uh[(size_t)NPAR * NIOU];
__device__ float g_fc[(size_t)NPAR * HH];

#define TS 68   // padded SMEM row stride (floats): conflict-free LDS.128, 16B-aligned

__device__ __forceinline__ float sigf(float v) { return 1.0f / (1.0f + __expf(-v)); }

// acc[i][j] += sum_k As[k][m0+i] * Ws[k][c0+j]   (As, Ws are [128][TS] transposed tiles)
__device__ __forceinline__ void mma64(const float* __restrict__ As,
                                      const float* __restrict__ Ws,
                                      float acc[4][4], int m0, int c0) {
#pragma unroll 8
    for (int k = 0; k < 128; k++) {
        float4 a = *(const float4*)(As + k * TS + m0);
        float4 b = *(const float4*)(Ws + k * TS + c0);
        acc[0][0] += a.x * b.x; acc[0][1] += a.x * b.y; acc[0][2] += a.x * b.z; acc[0][3] += a.x * b.w;
        acc[1][0] += a.y * b.x; acc[1][1] += a.y * b.y; acc[1][2] += a.y * b.z; acc[1][3] += a.y * b.w;
        acc[2][0] += a.z * b.x; acc[2][1] += a.z * b.y; acc[2][2] += a.z * b.z; acc[2][3] += a.z * b.w;
        acc[3][0] += a.w * b.x; acc[3][1] += a.w * b.y; acc[3][2] += a.w * b.z; acc[3][3] += a.w * b.w;
    }
}

// Stage a 128 x 64 weight chunk (row-major source, leading dim ld) into Ws[k][c]
__device__ __forceinline__ void loadW(float* __restrict__ Ws, const float* __restrict__ src,
                                      int ld, int colbase) {
    int t = threadIdx.x;
#pragma unroll
    for (int i = 0; i < 32; i++) {
        int idx = t + 256 * i;
        int k = idx >> 6, c = idx & 63;
        Ws[k * TS + c] = src[k * ld + colbase + c];
    }
}

// ---------------------------------------------------------------------------
// x_f precompute: g_xf[r] = x[r] @ W_f + b_f  for r < NPAR (parents only)
// ---------------------------------------------------------------------------
__global__ void xf_kernel(const float* __restrict__ x, const float* __restrict__ W_f,
                          const float* __restrict__ b_f) {
    extern __shared__ float sm[];
    float* As = sm;
    float* Ws = sm + 128 * TS;
    int t = threadIdx.x;
    int base = blockIdx.x << 6;
    int n_rows = NPAR - base; if (n_rows > 64) n_rows = 64;
    int m0 = (t & 15) * 4, c0 = (t >> 4) * 4;

#pragma unroll
    for (int i = 0; i < 32; i++) {
        int idx = t + 256 * i;
        int m = idx >> 7, k = idx & 127;
        float v = 0.f;
        if (m < n_rows) v = x[(size_t)(base + m) * EMBD + k];
        As[k * TS + m] = v;
    }
    for (int ch = 0; ch < 2; ch++) {
        __syncthreads();
        loadW(Ws, W_f, HH, ch * 64);
        __syncthreads();
        float acc[4][4] = {};
        mma64(As, Ws, acc, m0, c0);
#pragma unroll
        for (int i = 0; i < 4; i++)
#pragma unroll
            for (int j = 0; j < 4; j++) {
                int m = m0 + i, cc = ch * 64 + c0 + j;
                if (m < n_rows)
                    g_xf[(size_t)(base + m) * HH + cc] = acc[i][j] + b_f[cc];
            }
    }
}

// ---------------------------------------------------------------------------
// Fused per-level kernel:
//   iou = x@W_iou + b_iou (+ Uh_sum) -> c,h -> g = h@[U_iou|U_f]
//   f = sigmoid(x_f[parent] + g_f); segmented 8-row sums -> Uh_sum/fc_sum[parent]
// ---------------------------------------------------------------------------
__global__ void level_kernel(const float* __restrict__ x, const float* __restrict__ W_iou,
                             const float* __restrict__ b_iou, const float* __restrict__ U_iou,
                             const float* __restrict__ U_f,
                             int base0, int n_total, int read_sums, int has_parent) {
    extern __shared__ float sm[];
    float* As  = sm;                 // [128][TS] x^T, later h^T
    float* Ws  = sm + 128 * TS;      // [128][TS] weight chunk, reused as g_s[64][TS]
    float* iob = sm + 2 * 128 * TS;  // [64][384] iou buffer; [:,0:128] reused for c

    int t = threadIdx.x;
    int base = base0 + (blockIdx.x << 6);
    int n_rows = n_total - (blockIdx.x << 6); if (n_rows > 64) n_rows = 64;
    int m0 = (t & 15) * 4, c0 = (t >> 4) * 4;

    // load x tile (transposed, zero-padded)
#pragma unroll
    for (int i = 0; i < 32; i++) {
        int idx = t + 256 * i;
        int m = idx >> 7, k = idx & 127;
        float v = 0.f;
        if (m < n_rows) v = x[(size_t)(base + m) * EMBD + k];
        As[k * TS + m] = v;
    }

    // GEMM1: iou = x @ W_iou + b_iou (+ Uh_sum), 6 chunks of 64 cols
    for (int ch = 0; ch < 6; ch++) {
        __syncthreads();
        loadW(Ws, W_iou, NIOU, ch * 64);
        __syncthreads();
        float acc[4][4] = {};
        mma64(As, Ws, acc, m0, c0);
        int n0 = ch * 64;
#pragma unroll
        for (int i = 0; i < 4; i++)
#pragma unroll
            for (int j = 0; j < 4; j++) {
                int m = m0 + i, cc = n0 + c0 + j;
                float v = acc[i][j] + b_iou[cc];
                if (read_sums && m < n_rows) v += g_uh[(size_t)(base + m) * NIOU + cc];
                iob[m * NIOU + cc] = v;
            }
    }
    __syncthreads();

    // Activations: c = sig(i)*tanh(u)+fc_sum, h = sig(o)*tanh(c)
    // write h -> As (transposed), c -> iob[:,0:128]
#pragma unroll
    for (int i = 0; i < 32; i++) {
        int idx = t + 256 * i;
        int m = idx >> 7, j = idx & 127;
        float hn = 0.f, cn = 0.f;
        if (m < n_rows) {
            int r = base + m;
            float iv = iob[m * NIOU + j];
            float ov = iob[m * NIOU + 128 + j];
            float uv = iob[m * NIOU + 256 + j];
            float fcs = read_sums ? g_fc[(size_t)r * HH + j] : 0.f;
            cn = sigf(iv) * tanhf(uv) + fcs;
            hn = sigf(ov) * tanhf(cn);
            g_c[(size_t)r * HH + j] = cn;
            g_h[(size_t)r * HH + j] = hn;
        }
        As[j * TS + m] = hn;       // h^T for GEMM2 (zeros for padded rows)
        iob[m * NIOU + j] = cn;    // c (same (m,j) owner already consumed its i-value)
    }

    if (!has_parent) return;

    // GEMM2: g = h @ [U_iou(384) | U_f(128)], 8 chunks; reduce 8-row sibling groups
    int pbase = (base - 1) >> 3;
    for (int ch = 0; ch < 8; ch++) {
        __syncthreads();   // activation writes / previous g_s reads complete
        if (ch < 6) loadW(Ws, U_iou, NIOU, ch * 64);
        else        loadW(Ws, U_f, HH, (ch - 6) * 64);
        __syncthreads();
        float acc[4][4] = {};
        mma64(As, Ws, acc, m0, c0);
        __syncthreads();   // all Ws reads done -> reuse Ws as g_s
        if (ch < 6) {
#pragma unroll
            for (int i = 0; i < 4; i++)
#pragma unroll
                for (int j = 0; j < 4; j++)
                    Ws[(m0 + i) * TS + c0 + j] = acc[i][j];
        } else {
            int cb = (ch - 6) * 64;
#pragma unroll
            for (int i = 0; i < 4; i++)
#pragma unroll
                for (int j = 0; j < 4; j++) {
                    int m = m0 + i, cc = cb + c0 + j;
                    float v = 0.f;
                    if (m < n_rows) {
                        int r = base + m;
                        int par = (r - 1) >> 3;
                        float f = sigf(acc[i][j] + g_xf[(size_t)par * HH + cc]);
                        v = f * iob[m * NIOU + cc];   // f * c
                    }
                    Ws[(m0 + i) * TS + c0 + j] = v;
                }
        }
        __syncthreads();
        // segmented sum: 8 sibling rows -> 1 parent row, 8 parents x 64 cols
        for (int e = t; e < 512; e += 256) {
            int p = e >> 6, cc = e & 63;
            if (p * 8 < n_rows) {
                float s = 0.f;
#pragma unroll
                for (int q = 0; q < 8; q++) s += Ws[(p * 8 + q) * TS + cc];
                int prow = pbase + p;
                if (ch < 6) g_uh[(size_t)prow * NIOU + ch * 64 + cc] = s;
                else        g_fc[(size_t)prow * HH + (ch - 6) * 64 + cc] = s;
            }
        }
    }
}

// ---------------------------------------------------------------------------
// Output: out = tanh(LayerNorm(h @ W_out + b_out) * gamma + beta)
// ---------------------------------------------------------------------------
__global__ void out_kernel(const float* __restrict__ W_out, const float* __restrict__ b_out,
                           const float* __restrict__ gamma, const float* __restrict__ beta,
                           float* __restrict__ out) {
    extern __shared__ float sm[];
    float* As = sm;
    float* Ws = sm + 128 * TS;
    float* ys = sm + 2 * 128 * TS;   // [64][256]
    int t = threadIdx.x;
    int base = blockIdx.x << 6;
    int n_rows = NN - base; if (n_rows > 64) n_rows = 64;
    int m0 = (t & 15) * 4, c0 = (t >> 4) * 4;

#pragma unroll
    for (int i = 0; i < 32; i++) {
        int idx = t + 256 * i;
        int m = idx >> 7, k = idx & 127;
        float v = 0.f;
        if (m < n_rows) v = g_h[(size_t)(base + m) * HH + k];
        As[k * TS + m] = v;
    }
    for (int ch = 0; ch < 4; ch++) {
        __syncthreads();
        loadW(Ws, W_out, DDEC, ch * 64);
        __syncthreads();
        float acc[4][4] = {};
        mma64(As, Ws, acc, m0, c0);
#pragma unroll
        for (int i = 0; i < 4; i++)
#pragma unroll
            for (int j = 0; j < 4; j++) {
                int cc = ch * 64 + c0 + j;
                ys[(m0 + i) * DDEC + cc] = acc[i][j] + b_out[cc];
            }
    }
    __syncthreads();

    // LayerNorm + tanh: 4 lanes per row
    int m = t >> 2, q = t & 3;
    float s = 0.f, sq = 0.f;
    for (int j = q * 64; j < q * 64 + 64; j++) {
        float v = ys[m * DDEC + j];
        s += v; sq += v * v;
    }
    s  += __shfl_xor_sync(0xffffffffu, s, 1);  s  += __shfl_xor_sync(0xffffffffu, s, 2);
    sq += __shfl_xor_sync(0xffffffffu, sq, 1); sq += __shfl_xor_sync(0xffffffffu, sq, 2);
    float mu  = s * (1.f / 256.f);
    float var = sq * (1.f / 256.f) - mu * mu;
    float rs  = rsqrtf(var + 1e-5f);
    if (m < n_rows) {
        int r = base + m;
        for (int j = q * 64; j < q * 64 + 64; j++) {
            float v = (ys[m * DDEC + j] - mu) * rs * gamma[j] + beta[j];
            out[(size_t)r * DDEC + j] = tanhf(v);
        }
    }
}

// ---------------------------------------------------------------------------
extern "C" void kernel_launch(void* const* d_in, const int* in_sizes, int n_in,
                              void* d_out, int out_size) {
    const float* x = (const float*)d_in[0];
    // d_in[1]=parent, d_in[2]=levels (heap layout makes them redundant)
    // num_levels may appear as a size-1 scalar at index 3
    int wi = 3;
    if (n_in > 3 && in_sizes[3] <= 1) wi = 4;
    const float* W_iou = (const float*)d_in[wi + 0];
    const float* b_iou = (const float*)d_in[wi + 1];
    const float* U_iou = (const float*)d_in[wi + 2];
    const float* W_f   = (const float*)d_in[wi + 3];
    const float* b_f   = (const float*)d_in[wi + 4];
    const float* U_f   = (const float*)d_in[wi + 5];
    const float* W_out = (const float*)d_in[wi + 6];
    const float* b_out = (const float*)d_in[wi + 7];
    const float* gamma = (const float*)d_in[wi + 8];
    const float* beta  = (const float*)d_in[wi + 9];
    float* out = (float*)d_out;

    const int LEVEL_SMEM = (2 * 128 * TS + 64 * NIOU) * (int)sizeof(float);  // 167,936 B
    const int OUT_SMEM   = (2 * 128 * TS + 64 * DDEC) * (int)sizeof(float);  // 135,168 B
    const int XF_SMEM    = (2 * 128 * TS) * (int)sizeof(float);              //  69,632 B
    cudaFuncSetAttribute(level_kernel, cudaFuncAttributeMaxDynamicSharedMemorySize, LEVEL_SMEM);
    cudaFuncSetAttribute(out_kernel,   cudaFuncAttributeMaxDynamicSharedMemorySize, OUT_SMEM);
    cudaFuncSetAttribute(xf_kernel,    cudaFuncAttributeMaxDynamicSharedMemorySize, XF_SMEM);

    xf_kernel<<<(NPAR + 63) / 64, 256, XF_SMEM>>>(x, W_f, b_f);

    const int off[8] = {0, 1, 9, 73, 585, 4681, 37449, 299593};
    for (int l = 6; l >= 0; l--) {
        int base = off[l], n = off[l + 1] - off[l];
        int blocks = (n + 63) / 64;
        level_kernel<<<blocks, 256, LEVEL_SMEM>>>(x, W_iou, b_iou, U_iou, U_f,
                                                  base, n, (l < 6) ? 1 : 0, (l > 0) ? 1 : 0);
    }
    out_kernel<<<(NN + 63) / 64, 256, OUT_SMEM>>>(W_out, b_out, gamma, beta, out);
}

// round 4
// speedup vs baseline: 1.5996x; 1.5996x over previous
#include <cuda_runtime.h>
#include <math.h>

// Problem constants (fixed shapes)
#define NN    299593      // total nodes, complete 8-ary tree, 7 levels
#define HH    128         // D_ENC
#define EMBD  128         // D_EMB
#define NIOU  384         // 3*H
#define DDEC  256
#define NPAR  37449       // nodes at levels 0..5 (all parents) = off[6]

// Scratch (device globals: allocation-free per harness rules)
__device__ float g_h [(size_t)NN  * HH];
__device__ float g_c [(size_t)NN  * HH];
__device__ float g_xf[(size_t)NPAR * HH];
__device__ float g_uh[(size_t)NPAR * NIOU];
__device__ float g_fc[(size_t)NPAR * HH];

#define TS 68   // padded SMEM row stride (floats): conflict-free LDS.128, 16B-aligned

__device__ __forceinline__ float sigf(float v) { return 1.0f / (1.0f + __expf(-v)); }

// acc[i][j] += sum_k As[k][m0+i] * Ws[k][c0+j]   (As, Ws are [128][TS] transposed tiles)
__device__ __forceinline__ void mma64(const float* __restrict__ As,
                                      const float* __restrict__ Ws,
                                      float acc[4][4], int m0, int c0) {
#pragma unroll 8
    for (int k = 0; k < 128; k++) {
        float4 a = *(const float4*)(As + k * TS + m0);
        float4 b = *(const float4*)(Ws + k * TS + c0);
        acc[0][0] += a.x * b.x; acc[0][1] += a.x * b.y; acc[0][2] += a.x * b.z; acc[0][3] += a.x * b.w;
        acc[1][0] += a.y * b.x; acc[1][1] += a.y * b.y; acc[1][2] += a.y * b.z; acc[1][3] += a.y * b.w;
        acc[2][0] += a.z * b.x; acc[2][1] += a.z * b.y; acc[2][2] += a.z * b.z; acc[2][3] += a.z * b.w;
        acc[3][0] += a.w * b.x; acc[3][1] += a.w * b.y; acc[3][2] += a.w * b.z; acc[3][3] += a.w * b.w;
    }
}

// Stage a 128 x 64 weight chunk (row-major source, leading dim ld) into Ws[k][c]
__device__ __forceinline__ void loadW(float* __restrict__ Ws, const float* __restrict__ src,
                                      int ld, int colbase) {
    int t = threadIdx.x;
#pragma unroll
    for (int i = 0; i < 32; i++) {
        int idx = t + 256 * i;
        int k = idx >> 6, c = idx & 63;
        Ws[k * TS + c] = src[k * ld + colbase + c];
    }
}

// ---------------------------------------------------------------------------
// x_f precompute: g_xf[r] = x[r] @ W_f + b_f  for r < NPAR (parents only)
// ---------------------------------------------------------------------------
__global__ void xf_kernel(const float* __restrict__ x, const float* __restrict__ W_f,
                          const float* __restrict__ b_f) {
    extern __shared__ float sm[];
    float* As = sm;
    float* Ws = sm + 128 * TS;
    int t = threadIdx.x;
    int base = blockIdx.x << 6;
    int n_rows = NPAR - base; if (n_rows > 64) n_rows = 64;
    int m0 = (t & 15) * 4, c0 = (t >> 4) * 4;

#pragma unroll
    for (int i = 0; i < 32; i++) {
        int idx = t + 256 * i;
        int m = idx >> 7, k = idx & 127;
        float v = 0.f;
        if (m < n_rows) v = x[(size_t)(base + m) * EMBD + k];
        As[k * TS + m] = v;
    }
    for (int ch = 0; ch < 2; ch++) {
        __syncthreads();
        loadW(Ws, W_f, HH, ch * 64);
        __syncthreads();
        float acc[4][4] = {};
        mma64(As, Ws, acc, m0, c0);
#pragma unroll
        for (int i = 0; i < 4; i++)
#pragma unroll
            for (int j = 0; j < 4; j++) {
                int m = m0 + i, cc = ch * 64 + c0 + j;
                if (m < n_rows)
                    g_xf[(size_t)(base + m) * HH + cc] = acc[i][j] + b_f[cc];
            }
    }
}

// ---------------------------------------------------------------------------
// Fused per-level kernel:
//   iou = x@W_iou + b_iou (+ Uh_sum) -> c,h -> g = h@[U_iou|U_f]
//   f = sigmoid(x_f[parent] + g_f); segmented 8-row sums -> Uh_sum/fc_sum[parent]
// ---------------------------------------------------------------------------
__global__ void level_kernel(const float* __restrict__ x, const float* __restrict__ W_iou,
                             const float* __restrict__ b_iou, const float* __restrict__ U_iou,
                             const float* __restrict__ U_f,
                             int base0, int n_total, int read_sums, int has_parent) {
    extern __shared__ float sm[];
    float* As  = sm;                 // [128][TS] x^T, later h^T
    float* Ws  = sm + 128 * TS;      // [128][TS] weight chunk, reused as g_s[64][TS]
    float* iob = sm + 2 * 128 * TS;  // [64][384] iou buffer; [:,0:128] reused for c

    int t = threadIdx.x;
    int base = base0 + (blockIdx.x << 6);
    int n_rows = n_total - (blockIdx.x << 6); if (n_rows > 64) n_rows = 64;
    int m0 = (t & 15) * 4, c0 = (t >> 4) * 4;

    // load x tile (transposed, zero-padded)
#pragma unroll
    for (int i = 0; i < 32; i++) {
        int idx = t + 256 * i;
        int m = idx >> 7, k = idx & 127;
        float v = 0.f;
        if (m < n_rows) v = x[(size_t)(base + m) * EMBD + k];
        As[k * TS + m] = v;
    }

    // GEMM1: iou = x @ W_iou + b_iou (+ Uh_sum), 6 chunks of 64 cols
    for (int ch = 0; ch < 6; ch++) {
        __syncthreads();
        loadW(Ws, W_iou, NIOU, ch * 64);
        __syncthreads();
        float acc[4][4] = {};
        mma64(As, Ws, acc, m0, c0);
        int n0 = ch * 64;
#pragma unroll
        for (int i = 0; i < 4; i++)
#pragma unroll
            for (int j = 0; j < 4; j++) {
                int m = m0 + i, cc = n0 + c0 + j;
                float v = acc[i][j] + b_iou[cc];
                if (read_sums && m < n_rows) v += g_uh[(size_t)(base + m) * NIOU + cc];
                iob[m * NIOU + cc] = v;
            }
    }
    __syncthreads();

    // Activations: c = sig(i)*tanh(u)+fc_sum, h = sig(o)*tanh(c)
    // write h -> As (transposed), c -> iob[:,0:128]
#pragma unroll
    for (int i = 0; i < 32; i++) {
        int idx = t + 256 * i;
        int m = idx >> 7, j = idx & 127;
        float hn = 0.f, cn = 0.f;
        if (m < n_rows) {
            int r = base + m;
            float iv = iob[m * NIOU + j];
            float ov = iob[m * NIOU + 128 + j];
            float uv = iob[m * NIOU + 256 + j];
            float fcs = read_sums ? g_fc[(size_t)r * HH + j] : 0.f;
            cn = sigf(iv) * tanhf(uv) + fcs;
            hn = sigf(ov) * tanhf(cn);
            g_c[(size_t)r * HH + j] = cn;
            g_h[(size_t)r * HH + j] = hn;
        }
        As[j * TS + m] = hn;       // h^T for GEMM2 (zeros for padded rows)
        iob[m * NIOU + j] = cn;    // c (same (m,j) owner already consumed its i-value)
    }

    if (!has_parent) return;

    // GEMM2: g = h @ [U_iou(384) | U_f(128)], 8 chunks; reduce 8-row sibling groups
    int pbase = (base - 1) >> 3;
    for (int ch = 0; ch < 8; ch++) {
        __syncthreads();   // activation writes / previous g_s reads complete
        if (ch < 6) loadW(Ws, U_iou, NIOU, ch * 64);
        else        loadW(Ws, U_f, HH, (ch - 6) * 64);
        __syncthreads();
        float acc[4][4] = {};
        mma64(As, Ws, acc, m0, c0);
        __syncthreads();   // all Ws reads done -> reuse Ws as g_s
        if (ch < 6) {
#pragma unroll
            for (int i = 0; i < 4; i++)
#pragma unroll
                for (int j = 0; j < 4; j++)
                    Ws[(m0 + i) * TS + c0 + j] = acc[i][j];
        } else {
            int cb = (ch - 6) * 64;
#pragma unroll
            for (int i = 0; i < 4; i++)
#pragma unroll
                for (int j = 0; j < 4; j++) {
                    int m = m0 + i, cc = cb + c0 + j;
                    float v = 0.f;
                    if (m < n_rows) {
                        int r = base + m;
                        int par = (r - 1) >> 3;
                        float f = sigf(acc[i][j] + g_xf[(size_t)par * HH + cc]);
                        v = f * iob[m * NIOU + cc];   // f * c
                    }
                    Ws[(m0 + i) * TS + c0 + j] = v;
                }
        }
        __syncthreads();
        // segmented sum: 8 sibling rows -> 1 parent row, 8 parents x 64 cols
        for (int e = t; e < 512; e += 256) {
            int p = e >> 6, cc = e & 63;
            if (p * 8 < n_rows) {
                float s = 0.f;
#pragma unroll
                for (int q = 0; q < 8; q++) s += Ws[(p * 8 + q) * TS + cc];
                int prow = pbase + p;
                if (ch < 6) g_uh[(size_t)prow * NIOU + ch * 64 + cc] = s;
                else        g_fc[(size_t)prow * HH + (ch - 6) * 64 + cc] = s;
            }
        }
    }
}

// ---------------------------------------------------------------------------
// Output: out = tanh(LayerNorm(h @ W_out + b_out) * gamma + beta)
// ---------------------------------------------------------------------------
__global__ void out_kernel(const float* __restrict__ W_out, const float* __restrict__ b_out,
                           const float* __restrict__ gamma, const float* __restrict__ beta,
                           float* __restrict__ out) {
    extern __shared__ float sm[];
    float* As = sm;
    float* Ws = sm + 128 * TS;
    float* ys = sm + 2 * 128 * TS;   // [64][256]
    int t = threadIdx.x;
    int base = blockIdx.x << 6;
    int n_rows = NN - base; if (n_rows > 64) n_rows = 64;
    int m0 = (t & 15) * 4, c0 = (t >> 4) * 4;

#pragma unroll
    for (int i = 0; i < 32; i++) {
        int idx = t + 256 * i;
        int m = idx >> 7, k = idx & 127;
        float v = 0.f;
        if (m < n_rows) v = g_h[(size_t)(base + m) * HH + k];
        As[k * TS + m] = v;
    }
    for (int ch = 0; ch < 4; ch++) {
        __syncthreads();
        loadW(Ws, W_out, DDEC, ch * 64);
        __syncthreads();
        float acc[4][4] = {};
        mma64(As, Ws, acc, m0, c0);
#pragma unroll
        for (int i = 0; i < 4; i++)
#pragma unroll
            for (int j = 0; j < 4; j++) {
                int cc = ch * 64 + c0 + j;
                ys[(m0 + i) * DDEC + cc] = acc[i][j] + b_out[cc];
            }
    }
    __syncthreads();

    // LayerNorm + tanh: 4 lanes per row
    int m = t >> 2, q = t & 3;
    float s = 0.f, sq = 0.f;
    for (int j = q * 64; j < q * 64 + 64; j++) {
        float v = ys[m * DDEC + j];
        s += v; sq += v * v;
    }
    s  += __shfl_xor_sync(0xffffffffu, s, 1);  s  += __shfl_xor_sync(0xffffffffu, s, 2);
    sq += __shfl_xor_sync(0xffffffffu, sq, 1); sq += __shfl_xor_sync(0xffffffffu, sq, 2);
    float mu  = s * (1.f / 256.f);
    float var = sq * (1.f / 256.f) - mu * mu;
    float rs  = rsqrtf(var + 1e-5f);
    if (m < n_rows) {
        int r = base + m;
        for (int j = q * 64; j < q * 64 + 64; j++) {
            float v = (ys[m * DDEC + j] - mu) * rs * gamma[j] + beta[j];
            out[(size_t)r * DDEC + j] = tanhf(v);
        }
    }
}

// ---------------------------------------------------------------------------
extern "C" void kernel_launch(void* const* d_in, const int* in_sizes, int n_in,
                              void* d_out, int out_size) {
    const float* x = (const float*)d_in[0];
    // d_in[1]=parent, d_in[2]=levels (heap layout makes them redundant)
    // num_levels may appear as a size-1 scalar at index 3
    int wi = 3;
    if (n_in > 3 && in_sizes[3] <= 1) wi = 4;
    const float* W_iou = (const float*)d_in[wi + 0];
    const float* b_iou = (const float*)d_in[wi + 1];
    const float* U_iou = (const float*)d_in[wi + 2];
    const float* W_f   = (const float*)d_in[wi + 3];
    const float* b_f   = (const float*)d_in[wi + 4];
    const float* U_f   = (const float*)d_in[wi + 5];
    const float* W_out = (const float*)d_in[wi + 6];
    const float* b_out = (const float*)d_in[wi + 7];
    const float* gamma = (const float*)d_in[wi + 8];
    const float* beta  = (const float*)d_in[wi + 9];
    float* out = (float*)d_out;

    const int LEVEL_SMEM = (2 * 128 * TS + 64 * NIOU) * (int)sizeof(float);  // 167,936 B
    const int OUT_SMEM   = (2 * 128 * TS + 64 * DDEC) * (int)sizeof(float);  // 135,168 B
    const int XF_SMEM    = (2 * 128 * TS) * (int)sizeof(float);              //  69,632 B
    cudaFuncSetAttribute(level_kernel, cudaFuncAttributeMaxDynamicSharedMemorySize, LEVEL_SMEM);
    cudaFuncSetAttribute(out_kernel,   cudaFuncAttributeMaxDynamicSharedMemorySize, OUT_SMEM);
    cudaFuncSetAttribute(xf_kernel,    cudaFuncAttributeMaxDynamicSharedMemorySize, XF_SMEM);

    xf_kernel<<<(NPAR + 63) / 64, 256, XF_SMEM>>>(x, W_f, b_f);

    const int off[8] = {0, 1, 9, 73, 585, 4681, 37449, 299593};
    for (int l = 6; l >= 0; l--) {
        int base = off[l], n = off[l + 1] - off[l];
        int blocks = (n + 63) / 64;
        level_kernel<<<blocks, 256, LEVEL_SMEM>>>(x, W_iou, b_iou, U_iou, U_f,
                                                  base, n, (l < 6) ? 1 : 0, (l > 0) ? 1 : 0);
    }
    out_kernel<<<(NN + 63) / 64, 256, OUT_SMEM>>>(W_out, b_out, gamma, beta, out);
}